// round 6
// baseline (speedup 1.0000x reference)
#include <cuda_runtime.h>
#include <cuda_bf16.h>
#include <cstdint>

#define H            128
#define BASKET_LEN   200
#define NT           512               // 16 warps
#define PRODUCERS    7
#define IPB          29                // 7*29 = 203 >= 200
#define TAIL_RANK    7
#define NB           8                 // one cluster of 8 CTAs

__device__ __forceinline__ float fast_sigmoid(float x) {
    return __fdividef(1.0f, 1.0f + __expf(-x));
}
__device__ __forceinline__ float fast_tanh(float x) {
    const float t = __expf(-2.0f * x);
    return __fdividef(1.0f - t, 1.0f + t);
}

__global__ __launch_bounds__(NT, 1) __cluster_dims__(NB, 1, 1)
void encoder_rnn_cga(const int* __restrict__ basket,
                     const float* __restrict__ hidden,
                     const float* __restrict__ emb_table,
                     const float* __restrict__ w_ih,
                     const float* __restrict__ w_hh,
                     const float* __restrict__ b_ih,
                     const float* __restrict__ b_hh,
                     float* __restrict__ out,
                     int out_size)
{
    __shared__ float s_part[PRODUCERS][H];   // tail's inbox (DSMEM target)
    __shared__ float s_rows[15][H];          // producer gather rows
    __shared__ float s_emb[H];
    __shared__ float s_h[H];
    __shared__ float s_gi[3 * H];
    __shared__ float s_gh[3 * H];
    __shared__ float s_bih[3 * H];

    const int tid  = threadIdx.x;
    const int lane = tid & 31;
    const int w    = tid >> 5;
    const int blk  = blockIdx.x;             // == cluster rank (grid == cluster)

    if (blk < PRODUCERS) {
        // ================= producers: 29 items, 2 per warp =================
        float4 acc = make_float4(0.f, 0.f, 0.f, 0.f);
        if (w < 15) {
            const int i0 = 2 * w;
            const int i1 = 2 * w + 1;
            const int it0 = blk * IPB + i0;
            const int it1 = blk * IPB + i1;
            int idx0 = -1, idx1 = -1;
            if (lane == 0) {
                if (i0 < IPB && it0 < BASKET_LEN) idx0 = __ldg(&basket[it0]);
                if (i1 < IPB && it1 < BASKET_LEN) idx1 = __ldg(&basket[it1]);
            }
            idx0 = __shfl_sync(0xFFFFFFFFu, idx0, 0);
            idx1 = __shfl_sync(0xFFFFFFFFu, idx1, 0);
            if (idx0 >= 0) {
                const float4 v = __ldg(&reinterpret_cast<const float4*>(emb_table)[(size_t)idx0 * 32 + lane]);
                acc.x += v.x; acc.y += v.y; acc.z += v.z; acc.w += v.w;
            }
            if (idx1 >= 0) {
                const float4 v = __ldg(&reinterpret_cast<const float4*>(emb_table)[(size_t)idx1 * 32 + lane]);
                acc.x += v.x; acc.y += v.y; acc.z += v.z; acc.w += v.w;
            }
            reinterpret_cast<float4*>(s_rows)[w * 32 + lane] = acc;
        }
        __syncthreads();

        if (tid < H) {
            float a = 0.f;
            #pragma unroll
            for (int r = 0; r < 15; r++) a += s_rows[r][tid];
            // push partial straight into tail CTA's s_part[blk][tid]
            uint32_t laddr = (uint32_t)__cvta_generic_to_shared(&s_part[blk][tid]);
            asm volatile(
                "{\n\t"
                ".reg .u32 ra;\n\t"
                "mapa.shared::cluster.u32 ra, %0, %1;\n\t"
                "st.shared::cluster.f32 [ra], %2;\n\t"
                "}" :: "r"(laddr), "r"(TAIL_RANK), "f"(a) : "memory");
        }
        // release + join
        asm volatile("barrier.cluster.arrive.aligned;" ::: "memory");
        asm volatile("barrier.cluster.wait.aligned;"  ::: "memory");
        return;
    }

    // ======================= tail (rank 7) =======================
    // Pre-wait work: gh matvec, stage h/b_ih, preload half of w_ih rows.
    const float4 h4 = __ldg(&reinterpret_cast<const float4*>(hidden)[lane]);
    const int r0 = w * 24;                    // 16 warps * 24 rows = 384

    #pragma unroll
    for (int c = 0; c < 2; c++) {
        const int rb = r0 + c * 12;
        float p[12];
        #pragma unroll
        for (int j = 0; j < 12; j++) {
            const float4 a = __ldg(&reinterpret_cast<const float4*>(w_hh)[(size_t)(rb + j) * 32 + lane]);
            p[j] = a.x * h4.x + a.y * h4.y + a.z * h4.z + a.w * h4.w;
        }
        #pragma unroll
        for (int off = 16; off; off >>= 1)
            #pragma unroll
            for (int j = 0; j < 12; j++)
                p[j] += __shfl_xor_sync(0xFFFFFFFFu, p[j], off);
        #pragma unroll
        for (int j = 0; j < 12; j++)
            if (lane == j) s_gh[rb + j] = p[j] + __ldg(&b_hh[rb + j]);
    }

    if (tid < H)      s_h[tid]    = hidden[tid];
    if (tid < 3 * H)  s_bih[tid]  = __ldg(&b_ih[tid]);

    // preload first 12 w_ih rows of this warp into registers (latency off the tail path)
    float4 wa[12];
    #pragma unroll
    for (int j = 0; j < 12; j++)
        wa[j] = __ldg(&reinterpret_cast<const float4*>(w_ih)[(size_t)(r0 + j) * 32 + lane]);

    // join: partials become visible in LOCAL smem
    asm volatile("barrier.cluster.arrive.aligned;" ::: "memory");
    asm volatile("barrier.cluster.wait.aligned;"  ::: "memory");

    if (tid < H) {
        float a = 0.f;
        #pragma unroll
        for (int b = 0; b < PRODUCERS; b++) a += s_part[b][tid];
        s_emb[tid] = a * (1.0f / (float)H);
    }
    __syncthreads();

    // gi = w_ih @ emb : rows r0..r0+11 from regs, r0+12..r0+23 via L2
    {
        const float4 e4 = reinterpret_cast<const float4*>(s_emb)[lane];
        float p[24];
        #pragma unroll
        for (int j = 0; j < 12; j++)
            p[j] = wa[j].x * e4.x + wa[j].y * e4.y + wa[j].z * e4.z + wa[j].w * e4.w;
        #pragma unroll
        for (int j = 12; j < 24; j++) {
            const float4 a = __ldg(&reinterpret_cast<const float4*>(w_ih)[(size_t)(r0 + j) * 32 + lane]);
            p[j] = a.x * e4.x + a.y * e4.y + a.z * e4.z + a.w * e4.w;
        }
        #pragma unroll
        for (int off = 16; off; off >>= 1)
            #pragma unroll
            for (int j = 0; j < 24; j++)
                p[j] += __shfl_xor_sync(0xFFFFFFFFu, p[j], off);
        #pragma unroll
        for (int j = 0; j < 24; j++)
            if (lane == j) s_gi[r0 + j] = p[j];
    }
    __syncthreads();

    // gates + replicated output
    if (tid < H) {
        const float r = fast_sigmoid(s_gi[tid]         + s_bih[tid]         + s_gh[tid]);
        const float z = fast_sigmoid(s_gi[H + tid]     + s_bih[H + tid]     + s_gh[H + tid]);
        const float n = fast_tanh  (s_gi[2 * H + tid] + s_bih[2 * H + tid] + r * s_gh[2 * H + tid]);
        const float h_new = (1.0f - z) * n + z * s_h[tid];
        for (int o = tid; o < out_size; o += H)
            out[o] = h_new;
    }
}

extern "C" void kernel_launch(void* const* d_in, const int* in_sizes, int n_in,
                              void* d_out, int out_size)
{
    const int*   basket    = (const int*)  d_in[0];
    const float* hidden    = (const float*)d_in[1];
    const float* emb_table = (const float*)d_in[2];
    const float* w_ih      = (const float*)d_in[3];
    const float* w_hh      = (const float*)d_in[4];
    const float* b_ih      = (const float*)d_in[5];
    const float* b_hh      = (const float*)d_in[6];
    float* out = (float*)d_out;

    encoder_rnn_cga<<<NB, NT>>>(basket, hidden, emb_table,
                                w_ih, w_hh, b_ih, b_hh,
                                out, out_size);
}